// round 5
// baseline (speedup 1.0000x reference)
#include <cuda_runtime.h>
#include <cstdint>

#define NJ    24
#define NP    32768
#define NF    42
#define NR    16
#define DIN   126
#define HID   32
#define NIND  18
#define NOUTC 144

#define TILE_P 64          // points per block (4 warps x 16)

// shared layout (floats)
#define OFF_V    0                 // 4 warps * 16 pts * 132      = 8448
#define OFF_H    8448              // 4 warps * 16 pts * 36       = 2304
#define OFF_W1F  10752             // 16kt*4nt*32lane*2           = 4096
#define OFF_W2F  14848             // 4kt*16nt*32lane*2           = 4096
#define OFF_SF   18944             // [c][r][48]  3*16*48         = 2304
#define OFF_B1   21248             // 32
#define OFF_B2   21280             // 128 (padded)
#define SMEM_FLOATS 21408          // 85632 bytes

__device__ __forceinline__ uint32_t tf32r(float x) {
    uint32_t r; asm("cvt.rna.tf32.f32 %0, %1;" : "=r"(r) : "f"(x)); return r;
}

__device__ __forceinline__ void mma_tf32(float c[4], uint32_t a0, uint32_t a1,
                                         uint32_t a2, uint32_t a3,
                                         uint32_t b0, uint32_t b1) {
    asm volatile(
        "mma.sync.aligned.m16n8k8.row.col.f32.tf32.tf32.f32 "
        "{%0,%1,%2,%3}, {%4,%5,%6,%7}, {%8,%9}, {%0,%1,%2,%3};\n"
        : "+f"(c[0]), "+f"(c[1]), "+f"(c[2]), "+f"(c[3])
        : "r"(a0), "r"(a1), "r"(a2), "r"(a3), "r"(b0), "r"(b1));
}

extern "C" __global__ void __launch_bounds__(128)
v3d_mma_kernel(const float* __restrict__ pts,
               const float* __restrict__ feature,
               const float* __restrict__ ind,
               const float* __restrict__ w1,
               const float* __restrict__ b1,
               const float* __restrict__ w2,
               const float* __restrict__ b2,
               float* __restrict__ out)
{
    extern __shared__ float sm[];
    float* sfeat = sm + OFF_SF;
    float* b1s   = sm + OFF_B1;
    float* b2s   = sm + OFF_B2;
    uint32_t* w1f = (uint32_t*)(sm + OFF_W1F);
    uint32_t* w2f = (uint32_t*)(sm + OFF_W2F);

    const int j    = blockIdx.y;
    const int tid  = threadIdx.x;
    const int lane = tid & 31;
    const int warp = tid >> 5;

    // ---------------- Stage per-volume constants ----------------
    if (tid < HID) b1s[tid] = b1[j * HID + tid];
    if (tid < 128) b2s[tid] = (tid < DIN) ? b2[j * DIN + tid] : 0.0f;

    {   // W1 fragments: [kt][nt][lane]{b0,b1}, K padded 126->128
        const float* w1g = w1 + j * (DIN * HID);
        for (int idx = tid; idx < 2048; idx += 128) {
            int kt = idx >> 7, rem = idx & 127;
            int nt = rem >> 5, ln = rem & 31;
            int tg = ln & 3, gg = ln >> 2;
            int k0 = kt * 8 + tg, n = nt * 8 + gg;
            uint32_t x = (k0     < DIN) ? tf32r(w1g[k0 * HID + n])       : 0u;
            uint32_t y = (k0 + 4 < DIN) ? tf32r(w1g[(k0 + 4) * HID + n]) : 0u;
            *(uint2*)(w1f + idx * 2) = make_uint2(x, y);
        }
    }
    {   // W2 fragments: [kt2][nt][lane]{b0,b1}, N padded 126->128
        const float* w2g = w2 + j * (HID * DIN);
        for (int idx = tid; idx < 2048; idx += 128) {
            int kt2 = idx >> 9, rem = idx & 511;
            int nt = rem >> 5, ln = rem & 31;
            int tg = ln & 3, gg = ln >> 2;
            int k = kt2 * 8 + tg, n = nt * 8 + gg;
            uint32_t x = (n < DIN) ? tf32r(w2g[k * DIN + n])       : 0u;
            uint32_t y = (n < DIN) ? tf32r(w2g[(k + 4) * DIN + n]) : 0u;
            *(uint2*)(w2f + idx * 2) = make_uint2(x, y);
        }
    }
    {   // features [f][r][c] -> [c][r][fmap], fmap(f)= f<21 ? f : f+3 (aligned halves)
        for (int idx = tid; idx < 3 * NR * 48; idx += 128) sfeat[idx] = 0.0f;
        __syncthreads();
        const float* fg = feature + j * (NF * NR * 3);
        for (int idx = tid; idx < NF * NR * 3; idx += 128) {
            int f = idx / 48;
            int rr = (idx - f * 48) / 3;
            int c = idx - f * 48 - rr * 3;
            int fm = (f < 21) ? f : f + 3;
            sfeat[(c * NR + rr) * 48 + fm] = fg[idx];
        }
    }
    __syncthreads();

    const int p0  = blockIdx.x * TILE_P;
    const int pw0 = p0 + warp * 16;

    float*    Vw = sm + OFF_V + warp * (16 * 132);
    uint32_t* Vu = (uint32_t*)Vw;
    uint32_t* Hu = (uint32_t*)(sm + OFF_H + warp * (16 * 36));

    // ---------------- V generation (tf32 bits into Vu[pt][k], k=f*3+c) --------
    {
        const int pt_l = lane & 15;
        const int half = lane >> 4;
        const int fb   = half * 21;     // feature index base
        const int fo   = half * 24;     // smem offset base (aligned)
        const float* pp = pts + ((size_t)j * NP + pw0 + pt_l) * 3;
        float pc[3] = {pp[0], pp[1], pp[2]};

        #pragma unroll
        for (int c = 0; c < 3; ++c) {
            float x = fminf(fmaxf(fmaf(pc[c], 7.5f, 7.5f), 0.0f), 15.0f);
            int xi = (int)x; if (xi > NR - 2) xi = NR - 2;
            float wc = x - (float)xi;
            const float* row = sfeat + (c * NR + xi) * 48 + fo;
            #pragma unroll
            for (int i = 0; i < 5; ++i) {
                float4 g0 = *(const float4*)(row + i * 4);
                float4 g1 = *(const float4*)(row + 48 + i * 4);
                int kb = (fb + i * 4) * 3 + c;
                Vu[pt_l * 132 + kb    ] = tf32r(fmaf(wc, g1.x - g0.x, g0.x));
                Vu[pt_l * 132 + kb + 3] = tf32r(fmaf(wc, g1.y - g0.y, g0.y));
                Vu[pt_l * 132 + kb + 6] = tf32r(fmaf(wc, g1.z - g0.z, g0.z));
                Vu[pt_l * 132 + kb + 9] = tf32r(fmaf(wc, g1.w - g0.w, g0.w));
            }
            float s0 = row[20], s1 = row[48 + 20];
            Vu[pt_l * 132 + (fb + 20) * 3 + c] = tf32r(fmaf(wc, s1 - s0, s0));
        }
        // zero K padding 126..131
        #pragma unroll
        for (int t = 0; t < 3; ++t) Vu[pt_l * 132 + 126 + half * 3 + t] = 0u;
    }
    __syncwarp();

    const int tig = lane & 3;
    const int g   = lane >> 2;

    // ---------------- Layer 1: H[16,32] = relu(V[16,128] @ W1 + b1) -----------
    {
        float c1r[4][4];
        #pragma unroll
        for (int nt = 0; nt < 4; ++nt)
            #pragma unroll
            for (int e = 0; e < 4; ++e) c1r[nt][e] = 0.0f;

        #pragma unroll 4
        for (int kt = 0; kt < 16; ++kt) {
            const uint32_t* va = Vu + g * 132 + kt * 8 + tig;
            uint32_t a0 = va[0];
            uint32_t a1 = va[8 * 132];
            uint32_t a2 = va[4];
            uint32_t a3 = va[8 * 132 + 4];
            #pragma unroll
            for (int nt = 0; nt < 4; ++nt) {
                uint2 b = *(const uint2*)(w1f + ((kt * 4 + nt) * 32 + lane) * 2);
                mma_tf32(c1r[nt], a0, a1, a2, a3, b.x, b.y);
            }
        }
        #pragma unroll
        for (int nt = 0; nt < 4; ++nt) {
            int n0 = nt * 8;
            float2 bb = *(const float2*)(b1s + n0 + 2 * tig);
            float h0 = fmaxf(c1r[nt][0] + bb.x, 0.0f);
            float h1 = fmaxf(c1r[nt][1] + bb.y, 0.0f);
            float h2 = fmaxf(c1r[nt][2] + bb.x, 0.0f);
            float h3 = fmaxf(c1r[nt][3] + bb.y, 0.0f);
            *(uint2*)(Hu + g * 36 + n0 + 2 * tig)       = make_uint2(tf32r(h0), tf32r(h1));
            *(uint2*)(Hu + (g + 8) * 36 + n0 + 2 * tig) = make_uint2(tf32r(h2), tf32r(h3));
        }
    }
    __syncwarp();

    // ---------------- Layer 2: O[16,126] = H[16,32] @ W2 + b2 -----------------
    float* Obuf = Vw;   // reuse V region
    {
        uint32_t ha[16];
        #pragma unroll
        for (int kt2 = 0; kt2 < 4; ++kt2) {
            const uint32_t* hp = Hu + g * 36 + kt2 * 8 + tig;
            ha[kt2 * 4 + 0] = hp[0];
            ha[kt2 * 4 + 1] = hp[8 * 36];
            ha[kt2 * 4 + 2] = hp[4];
            ha[kt2 * 4 + 3] = hp[8 * 36 + 4];
        }
        #pragma unroll 4
        for (int nt2 = 0; nt2 < 16; ++nt2) {
            float cc[4] = {0.0f, 0.0f, 0.0f, 0.0f};
            #pragma unroll
            for (int kt2 = 0; kt2 < 4; ++kt2) {
                uint2 b = *(const uint2*)(w2f + ((kt2 * 16 + nt2) * 32 + lane) * 2);
                mma_tf32(cc, ha[kt2 * 4 + 0], ha[kt2 * 4 + 1],
                             ha[kt2 * 4 + 2], ha[kt2 * 4 + 3], b.x, b.y);
            }
            int ch = nt2 * 8 + 2 * tig;
            if (ch < DIN) {
                float2 bv = *(const float2*)(b2s + ch);
                float2 s0 = make_float2(cc[0] + bv.x, cc[1] + bv.y);
                float2 s1 = make_float2(cc[2] + bv.x, cc[3] + bv.y);
                *(float2*)(Obuf + g * 132 + ch)       = s0;
                *(float2*)(Obuf + (g + 8) * 132 + ch) = s1;
            }
        }
    }
    __syncwarp();

    // ---------------- Epilogue: coalesced gmem writes -------------------------
    {
        float*       outg = out + ((size_t)j * NP + pw0) * NOUTC;
        const float* indg = ind + ((size_t)j * NP + pw0) * NIND;
        #pragma unroll 1
        for (int pt = 0; pt < 16; ++pt) {
            if (lane < NIND) outg[pt * NOUTC + lane] = indg[pt * NIND + lane];
            #pragma unroll
            for (int r = 0; r < 4; ++r) {
                int ch = r * 32 + lane;
                if (ch < DIN) outg[pt * NOUTC + NIND + ch] = Obuf[pt * 132 + ch];
            }
        }
    }
}

extern "C" void kernel_launch(void* const* d_in, const int* in_sizes, int n_in,
                              void* d_out, int out_size)
{
    const float* pts     = (const float*)d_in[0];
    const float* feature = (const float*)d_in[1];
    const float* ind     = (const float*)d_in[2];
    const float* w1      = (const float*)d_in[3];
    const float* b1      = (const float*)d_in[4];
    const float* w2      = (const float*)d_in[5];
    const float* b2      = (const float*)d_in[6];
    float*       out     = (float*)d_out;

    const size_t smem = SMEM_FLOATS * sizeof(float);   // 85632 B
    cudaFuncSetAttribute(v3d_mma_kernel,
                         cudaFuncAttributeMaxDynamicSharedMemorySize, (int)smem);

    dim3 grid(NP / TILE_P, NJ);   // (512, 24)
    dim3 block(128);
    v3d_mma_kernel<<<grid, block, smem>>>(pts, feature, ind, w1, b1, w2, b2, out);
}

// round 6
// speedup vs baseline: 1.8043x; 1.8043x over previous
#include <cuda_runtime.h>
#include <cstdint>

#define NJ    24
#define NP    32768
#define NF    42
#define NR    16
#define DIN   126
#define HID   32
#define NIND  18
#define NOUTC 144

#define TILE_P 64          // points per tile (4 warps x 16)
#define NTILES 16          // tiles per block -> 1024 points per block

// shared layout (floats)
#define OFF_V    0                 // 4 warps * 16 pts * 132      = 8448
#define OFF_H    8448              // 4 warps * 16 pts * 36       = 2304
#define OFF_W1F  10752             // 16kt*4nt*32lane*2           = 4096
#define OFF_W2F  14848             // 4kt*16nt*32lane*2           = 4096
#define OFF_SF   18944             // [c][r][48]  3*16*48         = 2304
#define OFF_B1   21248             // 32
#define OFF_B2   21280             // 128 (padded)
#define SMEM_FLOATS 21408          // 85632 bytes

__device__ __forceinline__ uint32_t tf32r(float x) {
    uint32_t r; asm("cvt.rna.tf32.f32 %0, %1;" : "=r"(r) : "f"(x)); return r;
}

__device__ __forceinline__ void mma_tf32(float c[4], uint32_t a0, uint32_t a1,
                                         uint32_t a2, uint32_t a3,
                                         uint32_t b0, uint32_t b1) {
    asm volatile(
        "mma.sync.aligned.m16n8k8.row.col.f32.tf32.tf32.f32 "
        "{%0,%1,%2,%3}, {%4,%5,%6,%7}, {%8,%9}, {%0,%1,%2,%3};\n"
        : "+f"(c[0]), "+f"(c[1]), "+f"(c[2]), "+f"(c[3])
        : "r"(a0), "r"(a1), "r"(a2), "r"(a3), "r"(b0), "r"(b1));
}

extern "C" __global__ void __launch_bounds__(128)
v3d_mma_kernel(const float* __restrict__ pts,
               const float* __restrict__ feature,
               const float* __restrict__ ind,
               const float* __restrict__ w1,
               const float* __restrict__ b1,
               const float* __restrict__ w2,
               const float* __restrict__ b2,
               float* __restrict__ out)
{
    extern __shared__ float sm[];
    float* sfeat = sm + OFF_SF;
    float* b1s   = sm + OFF_B1;
    float* b2s   = sm + OFF_B2;
    uint32_t* w1f = (uint32_t*)(sm + OFF_W1F);
    uint32_t* w2f = (uint32_t*)(sm + OFF_W2F);

    const int j    = blockIdx.y;
    const int tid  = threadIdx.x;
    const int lane = tid & 31;
    const int warp = tid >> 5;

    // ---------------- Stage per-volume constants (ONCE per block) ----------------
    if (tid < HID) b1s[tid] = b1[j * HID + tid];
    if (tid < 128) b2s[tid] = (tid < DIN) ? b2[j * DIN + tid] : 0.0f;

    {   // W1 fragments: [kt][nt][lane]{b0,b1}, K padded 126->128
        const float* w1g = w1 + j * (DIN * HID);
        for (int idx = tid; idx < 2048; idx += 128) {
            int kt = idx >> 7, rem = idx & 127;
            int nt = rem >> 5, ln = rem & 31;
            int tg = ln & 3, gg = ln >> 2;
            int k0 = kt * 8 + tg, n = nt * 8 + gg;
            uint32_t x = (k0     < DIN) ? tf32r(w1g[k0 * HID + n])       : 0u;
            uint32_t y = (k0 + 4 < DIN) ? tf32r(w1g[(k0 + 4) * HID + n]) : 0u;
            *(uint2*)(w1f + idx * 2) = make_uint2(x, y);
        }
    }
    {   // W2 fragments: [kt2][nt][lane]{b0,b1}, N padded 126->128
        const float* w2g = w2 + j * (HID * DIN);
        for (int idx = tid; idx < 2048; idx += 128) {
            int kt2 = idx >> 9, rem = idx & 511;
            int nt = rem >> 5, ln = rem & 31;
            int tg = ln & 3, gg = ln >> 2;
            int k = kt2 * 8 + tg, n = nt * 8 + gg;
            uint32_t x = (n < DIN) ? tf32r(w2g[k * DIN + n])       : 0u;
            uint32_t y = (n < DIN) ? tf32r(w2g[(k + 4) * DIN + n]) : 0u;
            *(uint2*)(w2f + idx * 2) = make_uint2(x, y);
        }
    }
    {   // features [f][r][c] -> [c][r][fmap], fmap(f)= f<21 ? f : f+3 (aligned halves)
        for (int idx = tid; idx < 3 * NR * 48; idx += 128) sfeat[idx] = 0.0f;
        __syncthreads();
        const float* fg = feature + j * (NF * NR * 3);
        for (int idx = tid; idx < NF * NR * 3; idx += 128) {
            int f = idx / 48;
            int rr = (idx - f * 48) / 3;
            int c = idx - f * 48 - rr * 3;
            int fm = (f < 21) ? f : f + 3;
            sfeat[(c * NR + rr) * 48 + fm] = fg[idx];
        }
    }
    __syncthreads();

    float*    Vw = sm + OFF_V + warp * (16 * 132);
    uint32_t* Vu = (uint32_t*)Vw;
    uint32_t* Hu = (uint32_t*)(sm + OFF_H + warp * (16 * 36));

    const int tig = lane & 3;
    const int g   = lane >> 2;

    // ================= Tile loop: 16 tiles of 64 points =================
    #pragma unroll 1
    for (int t = 0; t < NTILES; ++t) {
        const int p0  = (blockIdx.x * NTILES + t) * TILE_P;
        const int pw0 = p0 + warp * 16;

        // ---------------- V generation (tf32 bits into Vu[pt][k], k=f*3+c) ----
        {
            const int pt_l = lane & 15;
            const int half = lane >> 4;
            const int fb   = half * 21;     // feature index base
            const int fo   = half * 24;     // smem offset base (aligned)
            const float* pp = pts + ((size_t)j * NP + pw0 + pt_l) * 3;
            float pc[3] = {pp[0], pp[1], pp[2]};

            #pragma unroll
            for (int c = 0; c < 3; ++c) {
                float x = fminf(fmaxf(fmaf(pc[c], 7.5f, 7.5f), 0.0f), 15.0f);
                int xi = (int)x; if (xi > NR - 2) xi = NR - 2;
                float wc = x - (float)xi;
                const float* row = sfeat + (c * NR + xi) * 48 + fo;
                #pragma unroll
                for (int i = 0; i < 5; ++i) {
                    float4 g0 = *(const float4*)(row + i * 4);
                    float4 g1 = *(const float4*)(row + 48 + i * 4);
                    int kb = (fb + i * 4) * 3 + c;
                    Vu[pt_l * 132 + kb    ] = tf32r(fmaf(wc, g1.x - g0.x, g0.x));
                    Vu[pt_l * 132 + kb + 3] = tf32r(fmaf(wc, g1.y - g0.y, g0.y));
                    Vu[pt_l * 132 + kb + 6] = tf32r(fmaf(wc, g1.z - g0.z, g0.z));
                    Vu[pt_l * 132 + kb + 9] = tf32r(fmaf(wc, g1.w - g0.w, g0.w));
                }
                float s0 = row[20], s1 = row[48 + 20];
                Vu[pt_l * 132 + (fb + 20) * 3 + c] = tf32r(fmaf(wc, s1 - s0, s0));
            }
            // zero K padding 126..131
            #pragma unroll
            for (int tt = 0; tt < 3; ++tt) Vu[pt_l * 132 + 126 + half * 3 + tt] = 0u;
        }
        __syncwarp();

        // ---------------- ind_feature copy early (overlaps MMAs) --------------
        {
            float*       outg = out + ((size_t)j * NP + pw0) * NOUTC;
            const float* indg = ind + ((size_t)j * NP + pw0) * NIND;
            #pragma unroll 1
            for (int idx = lane; idx < 16 * NIND; idx += 32) {
                int pp = idx / NIND;
                int cc = idx - pp * NIND;
                outg[pp * NOUTC + cc] = indg[idx];
            }
        }

        // ---------------- Layer 1: H[16,32] = relu(V[16,128] @ W1 + b1) -------
        {
            float c1r[4][4];
            #pragma unroll
            for (int nt = 0; nt < 4; ++nt)
                #pragma unroll
                for (int e = 0; e < 4; ++e) c1r[nt][e] = 0.0f;

            #pragma unroll 4
            for (int kt = 0; kt < 16; ++kt) {
                const uint32_t* va = Vu + g * 132 + kt * 8 + tig;
                uint32_t a0 = va[0];
                uint32_t a1 = va[8 * 132];
                uint32_t a2 = va[4];
                uint32_t a3 = va[8 * 132 + 4];
                #pragma unroll
                for (int nt = 0; nt < 4; ++nt) {
                    uint2 b = *(const uint2*)(w1f + ((kt * 4 + nt) * 32 + lane) * 2);
                    mma_tf32(c1r[nt], a0, a1, a2, a3, b.x, b.y);
                }
            }
            #pragma unroll
            for (int nt = 0; nt < 4; ++nt) {
                int n0 = nt * 8;
                float2 bb = *(const float2*)(b1s + n0 + 2 * tig);
                float h0 = fmaxf(c1r[nt][0] + bb.x, 0.0f);
                float h1 = fmaxf(c1r[nt][1] + bb.y, 0.0f);
                float h2 = fmaxf(c1r[nt][2] + bb.x, 0.0f);
                float h3 = fmaxf(c1r[nt][3] + bb.y, 0.0f);
                *(uint2*)(Hu + g * 36 + n0 + 2 * tig)       = make_uint2(tf32r(h0), tf32r(h1));
                *(uint2*)(Hu + (g + 8) * 36 + n0 + 2 * tig) = make_uint2(tf32r(h2), tf32r(h3));
            }
        }
        __syncwarp();

        // ---------------- Layer 2: O[16,126] = H[16,32] @ W2 + b2 -------------
        float* Obuf = Vw;   // reuse V region
        {
            uint32_t ha[16];
            #pragma unroll
            for (int kt2 = 0; kt2 < 4; ++kt2) {
                const uint32_t* hp = Hu + g * 36 + kt2 * 8 + tig;
                ha[kt2 * 4 + 0] = hp[0];
                ha[kt2 * 4 + 1] = hp[8 * 36];
                ha[kt2 * 4 + 2] = hp[4];
                ha[kt2 * 4 + 3] = hp[8 * 36 + 4];
            }
            #pragma unroll 4
            for (int nt2 = 0; nt2 < 16; ++nt2) {
                float cc[4] = {0.0f, 0.0f, 0.0f, 0.0f};
                #pragma unroll
                for (int kt2 = 0; kt2 < 4; ++kt2) {
                    uint2 b = *(const uint2*)(w2f + ((kt2 * 16 + nt2) * 32 + lane) * 2);
                    mma_tf32(cc, ha[kt2 * 4 + 0], ha[kt2 * 4 + 1],
                                 ha[kt2 * 4 + 2], ha[kt2 * 4 + 3], b.x, b.y);
                }
                int ch = nt2 * 8 + 2 * tig;
                if (ch < DIN) {
                    float2 bv = *(const float2*)(b2s + ch);
                    float2 s0 = make_float2(cc[0] + bv.x, cc[1] + bv.y);
                    float2 s1 = make_float2(cc[2] + bv.x, cc[3] + bv.y);
                    *(float2*)(Obuf + g * 132 + ch)       = s0;
                    *(float2*)(Obuf + (g + 8) * 132 + ch) = s1;
                }
            }
        }
        __syncwarp();

        // ---------------- Epilogue: coalesced gmem writes ---------------------
        {
            float* outg = out + ((size_t)j * NP + pw0) * NOUTC;
            #pragma unroll 1
            for (int pt = 0; pt < 16; ++pt) {
                #pragma unroll
                for (int r = 0; r < 4; ++r) {
                    int ch = r * 32 + lane;
                    if (ch < DIN) outg[pt * NOUTC + NIND + ch] = Obuf[pt * 132 + ch];
                }
            }
        }
        __syncwarp();   // Obuf/Vu reused next tile
    }
}

extern "C" void kernel_launch(void* const* d_in, const int* in_sizes, int n_in,
                              void* d_out, int out_size)
{
    const float* pts     = (const float*)d_in[0];
    const float* feature = (const float*)d_in[1];
    const float* ind     = (const float*)d_in[2];
    const float* w1      = (const float*)d_in[3];
    const float* b1      = (const float*)d_in[4];
    const float* w2      = (const float*)d_in[5];
    const float* b2      = (const float*)d_in[6];
    float*       out     = (float*)d_out;

    const size_t smem = SMEM_FLOATS * sizeof(float);   // 85632 B
    cudaFuncSetAttribute(v3d_mma_kernel,
                         cudaFuncAttributeMaxDynamicSharedMemorySize, (int)smem);

    dim3 grid(NP / (TILE_P * NTILES), NJ);   // (32, 24)
    dim3 block(128);
    v3d_mma_kernel<<<grid, block, smem>>>(pts, feature, ind, w1, b1, w2, b2, out);
}

// round 9
// speedup vs baseline: 2.2223x; 1.2317x over previous
#include <cuda_runtime.h>
#include <cstdint>

#define NJ    24
#define NP    32768
#define NF    42
#define NR    16
#define DIN   126
#define HID   32
#define NIND  18
#define NOUTC 144

#define NKT   18           // K tiles (K padded to 144 = 3 * 48)
#define NWARP 8            // warps per block
#define NTILES 8           // tiles per block; tile = 128 pts (8 warps x 16)

// shared layout (floats)
#define OFF_VO   0                         // 8 warps * 16*52   = 6656
#define OFF_H    6656                      // 8 warps * 16*36   = 4608
#define OFF_W1F  11264                     // 18kt*4nt*32*2     = 4608
#define OFF_W2F  15872                     // 4kt*16nt*32*2     = 4096
#define OFF_SF   19968                     // [c][r][48]        = 2304
#define OFF_B1   22272                     // 32
#define OFF_B2   22304                     // 128
#define SMEM_FLOATS 22432                  // 89728 bytes

__device__ __forceinline__ uint32_t tf32r(float x) {
    uint32_t r; asm("cvt.rna.tf32.f32 %0, %1;" : "=r"(r) : "f"(x)); return r;
}

__device__ __forceinline__ void mma_tf32(float c[4], uint32_t a0, uint32_t a1,
                                         uint32_t a2, uint32_t a3,
                                         uint32_t b0, uint32_t b1) {
    asm volatile(
        "mma.sync.aligned.m16n8k8.row.col.f32.tf32.tf32.f32 "
        "{%0,%1,%2,%3}, {%4,%5,%6,%7}, {%8,%9}, {%0,%1,%2,%3};\n"
        : "+f"(c[0]), "+f"(c[1]), "+f"(c[2]), "+f"(c[3])
        : "r"(a0), "r"(a1), "r"(a2), "r"(a3), "r"(b0), "r"(b1));
}

extern "C" __global__ void __launch_bounds__(256)
v3d_mma_kernel(const float* __restrict__ pts,
               const float* __restrict__ feature,
               const float* __restrict__ ind,
               const float* __restrict__ w1,
               const float* __restrict__ b1,
               const float* __restrict__ w2,
               const float* __restrict__ b2,
               float* __restrict__ out)
{
    extern __shared__ float sm[];
    float* sfeat = sm + OFF_SF;
    float* b1s   = sm + OFF_B1;
    float* b2s   = sm + OFF_B2;
    uint32_t* w1f = (uint32_t*)(sm + OFF_W1F);
    uint32_t* w2f = (uint32_t*)(sm + OFF_W2F);

    const int j    = blockIdx.y;
    const int tid  = threadIdx.x;
    const int lane = tid & 31;
    const int warp = tid >> 5;

    // ---------------- Stage per-volume constants (once per block) ----------------
    if (tid < HID) b1s[tid] = b1[j * HID + tid];
    if (tid < 128) b2s[tid] = (tid < DIN) ? b2[j * DIN + tid] : 0.0f;

    {   // W1 fragments over padded K=144 (col k = c*48+f), [kt][nt][lane]{b0,b1}
        const float* w1g = w1 + j * (DIN * HID);
        for (int idx = tid; idx < NKT * 128; idx += 256) {
            int kt = idx >> 7, rem = idx & 127;
            int nt = rem >> 5, ln = rem & 31;
            int tg = ln & 3, gg = ln >> 2;
            int n  = nt * 8 + gg;
            uint32_t v2[2];
            #pragma unroll
            for (int s = 0; s < 2; ++s) {
                int k = kt * 8 + tg + 4 * s;
                int c = k / 48, f = k - c * 48;
                v2[s] = (f < NF) ? tf32r(w1g[(f * 3 + c) * HID + n]) : 0u;
            }
            *(uint2*)(w1f + idx * 2) = make_uint2(v2[0], v2[1]);
        }
    }
    {   // W2 fragments: [kt2][nt][lane]{b0,b1}, N padded 126->128
        const float* w2g = w2 + j * (HID * DIN);
        for (int idx = tid; idx < 2048; idx += 256) {
            int kt2 = idx >> 9, rem = idx & 511;
            int nt = rem >> 5, ln = rem & 31;
            int tg = ln & 3, gg = ln >> 2;
            int k = kt2 * 8 + tg, n = nt * 8 + gg;
            uint32_t x = (n < DIN) ? tf32r(w2g[k * DIN + n])       : 0u;
            uint32_t y = (n < DIN) ? tf32r(w2g[(k + 4) * DIN + n]) : 0u;
            *(uint2*)(w2f + idx * 2) = make_uint2(x, y);
        }
    }
    {   // features [f][r][c] -> [c][r][f] (48-padded, f-contiguous)
        for (int idx = tid; idx < 3 * NR * 48; idx += 256) sfeat[idx] = 0.0f;
        __syncthreads();
        const float* fg = feature + j * (NF * NR * 3);
        for (int idx = tid; idx < NF * NR * 3; idx += 256) {
            int f = idx / 48;
            int rr = (idx - f * 48) / 3;
            int c = idx - f * 48 - rr * 3;
            sfeat[(c * NR + rr) * 48 + f] = fg[idx];
        }
    }
    __syncthreads();

    float*    Vw = sm + OFF_VO + warp * (16 * 52);
    uint32_t* Vu = (uint32_t*)Vw;
    uint32_t* Hu = (uint32_t*)(sm + OFF_H + warp * (16 * 36));

    const int tig  = lane & 3;
    const int g    = lane >> 2;
    const int pt_l = lane & 15;
    const int half = lane >> 4;

    // ================= Tile loop: 8 tiles of 128 points =================
    #pragma unroll 1
    for (int t = 0; t < NTILES; ++t) {
        const int pw0 = (blockIdx.x * NTILES + t) * 128 + warp * 16;

        // point coords for this lane's point
        const float* pp = pts + ((size_t)j * NP + pw0 + pt_l) * 3;
        float pc0 = pp[0], pc1 = pp[1], pc2 = pp[2];

        // ---------------- ind_feature copy early (overlaps compute) ----------
        {
            float*       outg = out + ((size_t)j * NP + pw0) * NOUTC;
            const float* indg = ind + ((size_t)j * NP + pw0) * NIND;
            #pragma unroll 1
            for (int idx = lane; idx < 16 * NIND; idx += 32) {
                int ppt = idx / NIND;
                int cc  = idx - ppt * NIND;
                outg[ppt * NOUTC + cc] = indg[idx];
            }
        }

        // ---------------- Layer 1 with chunked V generation -------------------
        float c1r[4][4];
        #pragma unroll
        for (int nt = 0; nt < 4; ++nt)
            #pragma unroll
            for (int e = 0; e < 4; ++e) c1r[nt][e] = 0.0f;

        #pragma unroll
        for (int c = 0; c < 3; ++c) {
            // --- generate V chunk for axis c: 16 pts x 48 cols (f 0..41 + pad)
            float pcc = (c == 0) ? pc0 : ((c == 1) ? pc1 : pc2);
            float x = fminf(fmaxf(fmaf(pcc, 7.5f, 7.5f), 0.0f), 15.0f);
            int xi = (int)x; if (xi > NR - 2) xi = NR - 2;
            float wc = x - (float)xi;
            const float* row = sfeat + (c * NR + xi) * 48;
            uint32_t* vrow = Vu + pt_l * 52;

            if (half == 0) {
                #pragma unroll
                for (int i = 0; i < 6; ++i) {
                    float4 g0 = *(const float4*)(row + i * 4);
                    float4 g1 = *(const float4*)(row + 48 + i * 4);
                    uint4 vv;
                    vv.x = tf32r(fmaf(wc, g1.x - g0.x, g0.x));
                    vv.y = tf32r(fmaf(wc, g1.y - g0.y, g0.y));
                    vv.z = tf32r(fmaf(wc, g1.z - g0.z, g0.z));
                    vv.w = tf32r(fmaf(wc, g1.w - g0.w, g0.w));
                    *(uint4*)(vrow + i * 4) = vv;
                }
            } else {
                #pragma unroll
                for (int i = 0; i < 4; ++i) {
                    float4 g0 = *(const float4*)(row + 24 + i * 4);
                    float4 g1 = *(const float4*)(row + 72 + i * 4);
                    uint4 vv;
                    vv.x = tf32r(fmaf(wc, g1.x - g0.x, g0.x));
                    vv.y = tf32r(fmaf(wc, g1.y - g0.y, g0.y));
                    vv.z = tf32r(fmaf(wc, g1.z - g0.z, g0.z));
                    vv.w = tf32r(fmaf(wc, g1.w - g0.w, g0.w));
                    *(uint4*)(vrow + 24 + i * 4) = vv;
                }
                float2 g0 = *(const float2*)(row + 40);
                float2 g1 = *(const float2*)(row + 88);
                uint2 vv;
                vv.x = tf32r(fmaf(wc, g1.x - g0.x, g0.x));
                vv.y = tf32r(fmaf(wc, g1.y - g0.y, g0.y));
                *(uint2*)(vrow + 40) = vv;
                *(uint2*)(vrow + 42) = make_uint2(0u, 0u);      // pad f=42,43
                *(uint4*)(vrow + 44) = make_uint4(0u, 0u, 0u, 0u); // pad f=44..47
            }
            __syncwarp();

            // --- consume chunk: 6 kt steps
            #pragma unroll
            for (int ktl = 0; ktl < 6; ++ktl) {
                const uint32_t* va = Vu + g * 52 + ktl * 8 + tig;
                uint32_t a0 = va[0];
                uint32_t a1 = va[8 * 52];
                uint32_t a2 = va[4];
                uint32_t a3 = va[8 * 52 + 4];
                int kt = c * 6 + ktl;
                #pragma unroll
                for (int nt = 0; nt < 4; ++nt) {
                    uint2 b = *(const uint2*)(w1f + ((kt * 4 + nt) * 32 + lane) * 2);
                    mma_tf32(c1r[nt], a0, a1, a2, a3, b.x, b.y);
                }
            }
            __syncwarp();   // chunk buffer reused next c
        }

        // bias + relu + tf32 -> H
        #pragma unroll
        for (int nt = 0; nt < 4; ++nt) {
            int n0 = nt * 8;
            float2 bb = *(const float2*)(b1s + n0 + 2 * tig);
            float h0 = fmaxf(c1r[nt][0] + bb.x, 0.0f);
            float h1 = fmaxf(c1r[nt][1] + bb.y, 0.0f);
            float h2 = fmaxf(c1r[nt][2] + bb.x, 0.0f);
            float h3 = fmaxf(c1r[nt][3] + bb.y, 0.0f);
            *(uint2*)(Hu + g * 36 + n0 + 2 * tig)       = make_uint2(tf32r(h0), tf32r(h1));
            *(uint2*)(Hu + (g + 8) * 36 + n0 + 2 * tig) = make_uint2(tf32r(h2), tf32r(h3));
        }
        __syncwarp();

        // ---------------- Layer 2 + staged epilogue ---------------------------
        uint32_t ha[16];
        #pragma unroll
        for (int kt2 = 0; kt2 < 4; ++kt2) {
            const uint32_t* hp = Hu + g * 36 + kt2 * 8 + tig;
            ha[kt2 * 4 + 0] = hp[0];
            ha[kt2 * 4 + 1] = hp[8 * 36];
            ha[kt2 * 4 + 2] = hp[4];
            ha[kt2 * 4 + 3] = hp[8 * 36 + 4];
        }

        float* outg = out + ((size_t)j * NP + pw0) * NOUTC;
        float* Ost  = Vw;    // reuse V chunk region (16*52 >= 16*36)

        #pragma unroll 1
        for (int r = 0; r < 4; ++r) {
            #pragma unroll
            for (int q = 0; q < 4; ++q) {
                int nt2 = r * 4 + q;
                float cc[4] = {0.0f, 0.0f, 0.0f, 0.0f};
                #pragma unroll
                for (int kt2 = 0; kt2 < 4; ++kt2) {
                    uint2 b = *(const uint2*)(w2f + ((kt2 * 16 + nt2) * 32 + lane) * 2);
                    mma_tf32(cc, ha[kt2 * 4 + 0], ha[kt2 * 4 + 1],
                                 ha[kt2 * 4 + 2], ha[kt2 * 4 + 3], b.x, b.y);
                }
                int chl = q * 8 + 2 * tig;          // 0..31 within round
                int ch  = r * 32 + chl;
                float2 bv = *(const float2*)(b2s + ch);
                *(float2*)(Ost + g * 36 + chl)       = make_float2(cc[0] + bv.x, cc[1] + bv.y);
                *(float2*)(Ost + (g + 8) * 36 + chl) = make_float2(cc[2] + bv.x, cc[3] + bv.y);
            }
            __syncwarp();
            int ch = r * 32 + lane;
            if (ch < DIN) {
                #pragma unroll 1
                for (int pt = 0; pt < 16; ++pt)
                    outg[pt * NOUTC + NIND + ch] = Ost[pt * 36 + lane];
            }
            __syncwarp();
        }
    }
}

extern "C" void kernel_launch(void* const* d_in, const int* in_sizes, int n_in,
                              void* d_out, int out_size)
{
    const float* pts     = (const float*)d_in[0];
    const float* feature = (const float*)d_in[1];
    const float* ind     = (const float*)d_in[2];
    const float* w1      = (const float*)d_in[3];
    const float* b1      = (const float*)d_in[4];
    const float* w2      = (const float*)d_in[5];
    const float* b2      = (const float*)d_in[6];
    float*       out     = (float*)d_out;

    const size_t smem = SMEM_FLOATS * sizeof(float);   // 89728 B
    cudaFuncSetAttribute(v3d_mma_kernel,
                         cudaFuncAttributeMaxDynamicSharedMemorySize, (int)smem);

    dim3 grid(NP / (128 * NTILES), NJ);   // (32, 24)
    dim3 block(256);
    v3d_mma_kernel<<<grid, block, smem>>>(pts, feature, ind, w1, b1, w2, b2, out);
}